// round 15
// baseline (speedup 1.0000x reference)
#include <cuda_runtime.h>
#include <math.h>

#define B_TOTAL 65536
#define OBS 64
#define ACTD 16
#define IND 145
#define HID 256
#define FEAT 128
#define NENV 64
#define EMB 32
#define ROWS 64
#define NTHREADS 512

typedef unsigned long long u64;

__device__ __forceinline__ u64 fma2(u64 a, u64 b, u64 c) {
    u64 d; asm("fma.rn.f32x2 %0,%1,%2,%3;" : "=l"(d) : "l"(a), "l"(b), "l"(c)); return d;
}
__device__ __forceinline__ u64 pack2(float x, float y) {
    u64 d; asm("mov.b64 %0,{%1,%2};" : "=l"(d) : "f"(x), "f"(y)); return d;
}
__device__ __forceinline__ void unpack2(u64 v, float& x, float& y) {
    asm("mov.b64 {%0,%1},%2;" : "=f"(x), "=f"(y) : "l"(v));
}
__device__ __forceinline__ void bar_half(int h) {
    asm volatile("bar.sync %0, %1;" :: "r"(h + 1), "r"(256) : "memory");
}

// ---- repacked weights (k-quads): Wq[j][c] = (W[4j..4j+3][c])
#define KQ0 37   // ceil(145/4), zero-padded
#define KQ1 64
#define KQ2 64
__device__ float4 g_w0q[KQ0 * 256];
__device__ float4 g_w1q[KQ1 * 256];
__device__ float4 g_w2q[KQ2 * 128];

__global__ void repack_kernel(const float* __restrict__ W0,
                              const float* __restrict__ W1,
                              const float* __restrict__ W2) {
    int i = blockIdx.x * 256 + threadIdx.x;
    if (i < KQ0 * 256) {
        int j = i >> 8, c = i & 255;
        float4 v;
        v.x = (4 * j + 0 < IND) ? W0[(4 * j + 0) * 256 + c] : 0.0f;
        v.y = (4 * j + 1 < IND) ? W0[(4 * j + 1) * 256 + c] : 0.0f;
        v.z = (4 * j + 2 < IND) ? W0[(4 * j + 2) * 256 + c] : 0.0f;
        v.w = (4 * j + 3 < IND) ? W0[(4 * j + 3) * 256 + c] : 0.0f;
        g_w0q[i] = v;
    } else if (i < KQ0 * 256 + KQ1 * 256) {
        int idx = i - KQ0 * 256;
        int j = idx >> 8, c = idx & 255;
        g_w1q[idx] = make_float4(W1[(4 * j + 0) * 256 + c], W1[(4 * j + 1) * 256 + c],
                                 W1[(4 * j + 2) * 256 + c], W1[(4 * j + 3) * 256 + c]);
    } else if (i < KQ0 * 256 + KQ1 * 256 + KQ2 * 128) {
        int idx = i - KQ0 * 256 - KQ1 * 256;
        int j = idx >> 7, c = idx & 127;
        g_w2q[idx] = make_float4(W2[(4 * j + 0) * 128 + c], W2[(4 * j + 1) * 128 + c],
                                 W2[(4 * j + 2) * 128 + c], W2[(4 * j + 3) * 128 + c]);
    }
}

// ---- shared memory layout (float offsets), all bases 16B-aligned ----
#define XS 148
#define HS 260
#define FS 132
#define OFF_X     0            // 64*148 = 9472 ; feat (64*132=8448) aliases
#define OFF_FEAT  0
#define OFF_H0    9472         // 64*260 = 16640 -> 26112
#define OFF_H1    26112        // -> 42752
#define OFF_TA    9472         // W tile half A: 128c*33f4 = 16896 fl -> 26368
#define OFF_TB    26368        // W tile half B -> 43264
#define OFF_EEMB  43264        // 2048 -> 45312
#define OFF_BESTA 45312        // 2048 -> 47360
#define OFF_BESTB 47360        // 2048 -> 49408
#define OFF_MINA  49408        // 64
#define OFF_MINB  49472        // 64
#define OFF_IDXA  49536        // 64 ints
#define OFF_IDXB  49600        // 64 ints
#define OFF_COEF  49664        // 64
#define SMEM_FLOATS 49728      // 198912 bytes, 1 CTA/SM

// Dense layer, row-major in/out, quad-k weights, packed f32x2 FMA,
// double-buffered w prefetch (hides L1-hit LDG latency).
template<int NJ, int KQ>
__device__ __forceinline__ void dense_q(
    const float* __restrict__ in_rm, int in_stride,
    const float4* __restrict__ Wq, const float* __restrict__ bias, int C,
    float* __restrict__ out_rm, int out_stride, int tid)
{
    const int tx = tid & 63;
    const int ty = tid >> 6;
    u64 acc[8][NJ];
#pragma unroll
    for (int jj = 0; jj < NJ; jj++) {
        float bb = __ldg(&bias[tx + 64 * jj]);
        u64 b2 = pack2(bb, 0.0f);
#pragma unroll
        for (int r = 0; r < 8; r++) acc[r][jj] = b2;
    }
    const float* xrow = in_rm + (ty * 8) * in_stride;
    const float4* wp = Wq + tx;

    ulonglong2 wc[NJ];
#pragma unroll
    for (int jj = 0; jj < NJ; jj++)
        wc[jj] = *(const ulonglong2*)&wp[64 * jj];

#pragma unroll 2
    for (int j = 0; j < KQ; j++) {
        ulonglong2 wn[NJ];
        if (j + 1 < KQ) {
            const float4* wq = wp + (size_t)(j + 1) * C;
#pragma unroll
            for (int jj = 0; jj < NJ; jj++)
                wn[jj] = *(const ulonglong2*)&wq[64 * jj];
        }
        const float* xk = xrow + 4 * j;
#pragma unroll
        for (int r = 0; r < 8; r++) {
            ulonglong2 xq = *(const ulonglong2*)(xk + r * in_stride);
#pragma unroll
            for (int jj = 0; jj < NJ; jj++) {
                acc[r][jj] = fma2(xq.x, wc[jj].x, acc[r][jj]);
                acc[r][jj] = fma2(xq.y, wc[jj].y, acc[r][jj]);
            }
        }
#pragma unroll
        for (int jj = 0; jj < NJ; jj++) wc[jj] = wn[jj];
    }
#pragma unroll
    for (int r = 0; r < 8; r++) {
#pragma unroll
        for (int jj = 0; jj < NJ; jj++) {
            float lo, hi; unpack2(acc[r][jj], lo, hi);
            float s = lo + hi;
            out_rm[(ty * 8 + r) * out_stride + tx + 64 * jj] = fmaxf(s, 0.01f * s);
        }
    }
}

extern __shared__ float sm[];

__global__ void __launch_bounds__(NTHREADS, 1)
udp_encoder_kernel(
    const float* __restrict__ obs,  const float* __restrict__ act,
    const float* __restrict__ obs2, const float* __restrict__ rew,
    const float* __restrict__ b0,   const float* __restrict__ b1,
    const float* __restrict__ b2,   const float* __restrict__ Wp,
    const float* __restrict__ ee,   const float* __restrict__ sig,
    float* __restrict__ out)
{
    const int tid = threadIdx.x;
    const size_t row0 = (size_t)blockIdx.x * ROWS;

    // ---- stage e_emb + sigma coefficients ----
    for (int i = tid; i < NENV * EMB; i += NTHREADS) sm[OFF_EEMB + i] = ee[i];
    if (tid < NENV) {
        float s = sig[tid];
        sm[OFF_COEF + tid] = -1.0f / (64.0f * s * s);
    }

    // ---- build row-major input tile X[r][k], stride 148, k=145..147 zero ----
    for (int i = tid; i < ROWS * OBS; i += NTHREADS) {
        int r = i >> 6, k = i & 63;
        float o  = obs [(row0 + r) * OBS + k];
        float o2 = obs2[(row0 + r) * OBS + k];
        sm[OFF_X + r * XS + k]      = o;
        sm[OFF_X + r * XS + 64 + k] = o2 - o;
    }
    for (int i = tid; i < ROWS * ACTD; i += NTHREADS) {
        int r = i >> 4, k = i & 15;
        sm[OFF_X + r * XS + 128 + k] = act[(row0 + r) * ACTD + k];
    }
    if (tid < ROWS) {
        sm[OFF_X + tid * XS + 144] = rew[row0 + tid];
        sm[OFF_X + tid * XS + 145] = 0.0f;
        sm[OFF_X + tid * XS + 146] = 0.0f;
        sm[OFF_X + tid * XS + 147] = 0.0f;
    }
    __syncthreads();

    // ---- MLP ----
    dense_q<4, KQ0>(sm + OFF_X,  XS, g_w0q, b0, 256, sm + OFF_H0,   HS, tid);
    __syncthreads();
    dense_q<4, KQ1>(sm + OFF_H0, HS, g_w1q, b1, 256, sm + OFF_H1,   HS, tid);
    __syncthreads();
    dense_q<2, KQ2>(sm + OFF_H1, HS, g_w2q, b2, 128, sm + OFF_FEAT, FS, tid);
    __syncthreads();   // H0/H1 now dead; feat final

    // ==== projection: two independent halves over env-groups ====
    const int lane = tid & 31;
    const int wrp  = tid >> 5;          // 16 warps
    const int h    = wrp >> 3;          // half 0: g 0..7 ; half 1: g 8..15
    const int wr   = wrp & 7;           // row-warp within half, 8 rows each
    const int nl   = lane >> 3;         // env within group (0..3)
    const int eb   = lane & 7;          // lane's emb dims: e = eb + 8j
    const int r0   = wr * 8;

    float mind[8]; int midx[8];
#pragma unroll
    for (int i = 0; i < 8; i++) { mind[i] = 3.0e38f; midx[i] = 0; }

    float4* wt = (float4*)(sm + (h ? OFF_TB : OFF_TA));   // [c][kq], stride 33 f4
    float*  bestH = sm + (h ? OFF_BESTB : OFF_BESTA);
    const float4* WpQ = (const float4*)Wp;                // [n][e][kq]
    const float* fbase = sm + OFF_FEAT + r0 * FS;
    const int cbase = nl * 32 + eb;

    for (int gg = 0; gg < 8; gg++) {
        const int g = h * 8 + gg;
        bar_half(h);
        // stage W tile: warp wr covers c = wr + 8*i; lane = kq
#pragma unroll
        for (int i = 0; i < 16; i++) {
            int c = wr + 8 * i;
            int n_l = c >> 5, e = c & 31;
            float4 v = WpQ[((size_t)(g * 4 + n_l) * EMB + e) * 32 + lane];
            wt[c * 33 + lane] = v;
        }
        bar_half(h);

        const int n = g * 4 + nl;
        float eev[4];
#pragma unroll
        for (int j = 0; j < 4; j++) eev[j] = sm[OFF_EEMB + n * EMB + eb + 8 * j];
        float cf = sm[OFF_COEF + n];

        u64 acc[8][4];
#pragma unroll
        for (int r = 0; r < 8; r++)
#pragma unroll
            for (int j = 0; j < 4; j++) acc[r][j] = 0ULL;

        // double-buffered w prefetch over kq
        const float4* wl = wt + cbase * 33;   // + (8j)*33 + kq
        ulonglong2 wc[4];
#pragma unroll
        for (int j = 0; j < 4; j++)
            wc[j] = *(const ulonglong2*)&wl[j * 8 * 33];

#pragma unroll 2
        for (int kq = 0; kq < 32; kq++) {
            ulonglong2 wn[4];
            if (kq + 1 < 32) {
#pragma unroll
                for (int j = 0; j < 4; j++)
                    wn[j] = *(const ulonglong2*)&wl[j * 8 * 33 + kq + 1];
            }
            const float* xk = fbase + 4 * kq;
#pragma unroll
            for (int r = 0; r < 8; r++) {
                ulonglong2 xq = *(const ulonglong2*)(xk + r * FS);
#pragma unroll
                for (int j = 0; j < 4; j++) {
                    acc[r][j] = fma2(xq.x, wc[j].x, acc[r][j]);
                    acc[r][j] = fma2(xq.y, wc[j].y, acc[r][j]);
                }
            }
#pragma unroll
            for (int j = 0; j < 4; j++) wc[j] = wn[j];
        }

        // epilogue: distances, argmin, winner-copy — all in-warp
#pragma unroll
        for (int r = 0; r < 8; r++) {
            float f[4];
#pragma unroll
            for (int j = 0; j < 4; j++) {
                float lo, hi; unpack2(acc[r][j], lo, hi);
                f[j] = lo + hi;
            }
            float ss = 0.0f;
#pragma unroll
            for (int j = 0; j < 4; j++) {
                float d = f[j] - eev[j];
                ss = fmaf(d, d, ss);
            }
            ss += __shfl_xor_sync(0xffffffffu, ss, 1);
            ss += __shfl_xor_sync(0xffffffffu, ss, 2);
            ss += __shfl_xor_sync(0xffffffffu, ss, 4);
            float dv = expf(ss * cf);
            if (eb == 0)
                out[(size_t)B_TOTAL * 66 + (row0 + r0 + r) * 64 + n] = dv;

            float dred = (eb == 0) ? dv : 3.0e38f;
            int   nred = n;
#pragma unroll
            for (int s = 8; s <= 16; s <<= 1) {
                float d2 = __shfl_xor_sync(0xffffffffu, dred, s);
                int   n2 = __shfl_xor_sync(0xffffffffu, nred, s);
                if (d2 < dred || (d2 == dred && n2 < nred)) { dred = d2; nred = n2; }
            }
            float wd = __shfl_sync(0xffffffffu, dred, 0);
            int   wn2 = __shfl_sync(0xffffffffu, nred, 0);

            if (wd < mind[r]) {
                mind[r] = wd; midx[r] = wn2;
                if (nl == (wn2 & 3)) {
#pragma unroll
                    for (int j = 0; j < 4; j++)
                        bestH[(r0 + r) * EMB + eb + 8 * j] = f[j];
                }
            }
        }
    }

    // publish per-half argmin state
    if (lane == 0) {
        float* minH = sm + (h ? OFF_MINB : OFF_MINA);
        int*   idxH = (int*)sm + (h ? OFF_IDXB : OFF_IDXA);
#pragma unroll
        for (int r = 0; r < 8; r++) {
            minH[r0 + r] = mind[r];
            idxH[r0 + r] = midx[r];
        }
    }
    __syncthreads();

    // ==== combine halves + final outputs: each warp handles 4 rows ====
#pragma unroll
    for (int r = 0; r < 4; r++) {
        int row = wrp * 4 + r;
        size_t grow = row0 + row;
        float da = sm[OFF_MINA + row], db = sm[OFF_MINB + row];
        bool bwin = db < da;   // half A owns smaller n -> wins ties
        float d = bwin ? db : da;
        int m = bwin ? ((int*)sm)[OFF_IDXB + row] : ((int*)sm)[OFF_IDXA + row];
        float e = bwin ? sm[OFF_BESTB + row * EMB + lane]
                       : sm[OFF_BESTA + row * EMB + lane];
        out[grow * EMB + lane] = e;                                                    // chosen_embedding
        out[(size_t)B_TOTAL * 34 + grow * EMB + lane] = sm[OFF_EEMB + m * EMB + lane]; // chosen_mean
        if (lane == 0) {
            out[(size_t)B_TOTAL * 32 + grow] = d;          // chosen_dist
            out[(size_t)B_TOTAL * 33 + grow] = (float)m;   // idx
        }
    }
}

extern "C" void kernel_launch(void* const* d_in, const int* in_sizes, int n_in,
                              void* d_out, int out_size) {
    const float* obs  = (const float*)d_in[0];
    const float* act  = (const float*)d_in[1];
    const float* obs2 = (const float*)d_in[2];
    const float* rew  = (const float*)d_in[3];
    const float* W0   = (const float*)d_in[4];
    const float* b0   = (const float*)d_in[5];
    const float* W1   = (const float*)d_in[6];
    const float* b1   = (const float*)d_in[7];
    const float* W2   = (const float*)d_in[8];
    const float* b2   = (const float*)d_in[9];
    const float* Wp   = (const float*)d_in[10];
    const float* ee   = (const float*)d_in[11];
    const float* sig  = (const float*)d_in[12];
    float* out = (float*)d_out;

    int total = KQ0 * 256 + KQ1 * 256 + KQ2 * 128;
    repack_kernel<<<(total + 255) / 256, 256>>>(W0, W1, W2);

    const size_t smem_bytes = (size_t)SMEM_FLOATS * sizeof(float); // 198912
    cudaFuncSetAttribute(udp_encoder_kernel,
                         cudaFuncAttributeMaxDynamicSharedMemorySize, (int)smem_bytes);

    dim3 grid(B_TOTAL / ROWS);   // 1024 blocks
    dim3 block(NTHREADS);
    udp_encoder_kernel<<<grid, block, smem_bytes>>>(
        obs, act, obs2, rew, b0, b1, b2, Wp, ee, sig, out);
}

// round 16
// speedup vs baseline: 1.0194x; 1.0194x over previous
#include <cuda_runtime.h>
#include <math.h>
#include <stdint.h>

#define B_TOTAL 65536
#define OBS 64
#define ACTD 16
#define IND 145
#define HID 256
#define FEAT 128
#define NENV 64
#define EMB 32
#define ROWS 64
#define NTHREADS 512

typedef unsigned long long u64;

__device__ __forceinline__ u64 fma2(u64 a, u64 b, u64 c) {
    u64 d; asm("fma.rn.f32x2 %0,%1,%2,%3;" : "=l"(d) : "l"(a), "l"(b), "l"(c)); return d;
}
__device__ __forceinline__ u64 pack2(float x, float y) {
    u64 d; asm("mov.b64 %0,{%1,%2};" : "=l"(d) : "f"(x), "f"(y)); return d;
}
__device__ __forceinline__ void unpack2(u64 v, float& x, float& y) {
    asm("mov.b64 {%0,%1},%2;" : "=f"(x), "=f"(y) : "l"(v));
}
__device__ __forceinline__ void bar_half(int h) {
    asm volatile("bar.sync %0, %1;" :: "r"(h + 1), "r"(256) : "memory");
}
__device__ __forceinline__ void cp_async16(uint32_t saddr, const void* gptr) {
    asm volatile("cp.async.cg.shared.global [%0], [%1], 16;" :: "r"(saddr), "l"(gptr));
}
__device__ __forceinline__ void cp_commit() {
    asm volatile("cp.async.commit_group;" ::: "memory");
}
template<int N> __device__ __forceinline__ void cp_wait() {
    asm volatile("cp.async.wait_group %0;" :: "n"(N) : "memory");
}
__device__ __forceinline__ uint32_t s2u(const void* p) {
    return (uint32_t)__cvta_generic_to_shared(p);
}

// ---- repacked weights (k-quads): Wq[j][c] = (W[4j..4j+3][c]); layer0 padded to 40 quads
#define KQ0 40
#define KQ1 64
#define KQ2 64
__device__ float4 g_w0q[KQ0 * 256];
__device__ float4 g_w1q[KQ1 * 256];
__device__ float4 g_w2q[KQ2 * 128];

__global__ void repack_kernel(const float* __restrict__ W0,
                              const float* __restrict__ W1,
                              const float* __restrict__ W2) {
    int i = blockIdx.x * 256 + threadIdx.x;
    if (i < KQ0 * 256) {
        int j = i >> 8, c = i & 255;
        float4 v;
        v.x = (4 * j + 0 < IND) ? W0[(4 * j + 0) * 256 + c] : 0.0f;
        v.y = (4 * j + 1 < IND) ? W0[(4 * j + 1) * 256 + c] : 0.0f;
        v.z = (4 * j + 2 < IND) ? W0[(4 * j + 2) * 256 + c] : 0.0f;
        v.w = (4 * j + 3 < IND) ? W0[(4 * j + 3) * 256 + c] : 0.0f;
        g_w0q[i] = v;
    } else if (i < KQ0 * 256 + KQ1 * 256) {
        int idx = i - KQ0 * 256;
        int j = idx >> 8, c = idx & 255;
        g_w1q[idx] = make_float4(W1[(4 * j + 0) * 256 + c], W1[(4 * j + 1) * 256 + c],
                                 W1[(4 * j + 2) * 256 + c], W1[(4 * j + 3) * 256 + c]);
    } else if (i < KQ0 * 256 + KQ1 * 256 + KQ2 * 128) {
        int idx = i - KQ0 * 256 - KQ1 * 256;
        int j = idx >> 7, c = idx & 127;
        g_w2q[idx] = make_float4(W2[(4 * j + 0) * 128 + c], W2[(4 * j + 1) * 128 + c],
                                 W2[(4 * j + 2) * 128 + c], W2[(4 * j + 3) * 128 + c]);
    }
}

// ---- shared memory layout (float offsets), all bases 16B-aligned ----
#define XS 164                 // X row stride: 160 k (40 quads) + pad
#define HS 256
#define FS 132
#define OFF_X     0            // 64*164 = 10496 ; feat (64*132=8448) aliases
#define OFF_FEAT  0
#define OFF_H0    10496        // 64*256 = 16384 -> 26880
#define OFF_H1    26880        // -> 43264
#define OFF_STG   43264        // 2 x 1024 float4 = 8192 floats -> 51456
#define OFF_TA    10496        // proj W tile half A: 16896 fl -> 27392 (H0+H1 head; dead)
#define OFF_TB    27392        // -> 44288 (H1 tail + STG head; dead)
#define OFF_EEMB  51456        // 2048 -> 53504
#define OFF_BESTA 53504        // 2048 -> 55552
#define OFF_BESTB 55552        // 2048 -> 57600
#define OFF_MINA  57600        // 64
#define OFF_MINB  57664        // 64
#define OFF_IDXA  57728        // 64 ints
#define OFF_IDXB  57792        // 64 ints
#define OFF_COEF  57856        // 64
#define SMEM_FLOATS 57920      // 231680 bytes, 1 CTA/SM

// Dense layer with cp.async double-buffered weight chunks (4 k-quads per chunk).
// Weight chunk lives in smem: [jj4][c] float4, read via conflict-free LDS.128.
// tx = tid&63 -> cols {tx+64jj}; ty = tid>>6 (0..7) -> rows [ty*8, ty*8+8)
template<int NJ, int NCH>
__device__ __forceinline__ void dense_cp(
    const float* __restrict__ in_rm, int in_stride,
    const float4* __restrict__ WqG, const float* __restrict__ bias, int C,
    float* __restrict__ out_rm, int out_stride,
    float4* __restrict__ sb0, float4* __restrict__ sb1, int tid)
{
    const int tx = tid & 63;
    const int ty = tid >> 6;

    // stage chunk 0 and 1
    {
        const int nel = 4 * C;
        for (int i = tid; i < nel; i += NTHREADS)
            cp_async16(s2u(sb0 + i), WqG + i);
        cp_commit();
        if (NCH > 1) {
            const float4* src = WqG + nel;
            for (int i = tid; i < nel; i += NTHREADS)
                cp_async16(s2u(sb1 + i), src + i);
            cp_commit();
        }
    }

    u64 acc[8][NJ];
#pragma unroll
    for (int jj = 0; jj < NJ; jj++) {
        float bb = __ldg(&bias[tx + 64 * jj]);
        u64 b2 = pack2(bb, 0.0f);
#pragma unroll
        for (int r = 0; r < 8; r++) acc[r][jj] = b2;
    }
    const float* xrow = in_rm + (ty * 8) * in_stride;

    for (int ch = 0; ch < NCH; ch++) {
        float4* cur = (ch & 1) ? sb1 : sb0;
        if (ch + 2 <= NCH) cp_wait<1>(); else cp_wait<0>();
        __syncthreads();

#pragma unroll
        for (int jj4 = 0; jj4 < 4; jj4++) {
            ulonglong2 w[NJ];
#pragma unroll
            for (int jj = 0; jj < NJ; jj++)
                w[jj] = *(const ulonglong2*)&cur[jj4 * C + tx + 64 * jj];
            const float* xk = xrow + 16 * ch + 4 * jj4;
#pragma unroll
            for (int r = 0; r < 8; r++) {
                ulonglong2 xq = *(const ulonglong2*)(xk + r * in_stride);
#pragma unroll
                for (int jj = 0; jj < NJ; jj++) {
                    acc[r][jj] = fma2(xq.x, w[jj].x, acc[r][jj]);
                    acc[r][jj] = fma2(xq.y, w[jj].y, acc[r][jj]);
                }
            }
        }
        __syncthreads();   // readers done -> buffer reusable

        if (ch + 2 < NCH) {
            const float4* src = WqG + (size_t)(ch + 2) * 4 * C;
            const int nel = 4 * C;
            for (int i = tid; i < nel; i += NTHREADS)
                cp_async16(s2u(cur + i), src + i);
            cp_commit();
        }
    }

#pragma unroll
    for (int r = 0; r < 8; r++) {
#pragma unroll
        for (int jj = 0; jj < NJ; jj++) {
            float lo, hi; unpack2(acc[r][jj], lo, hi);
            float s = lo + hi;
            out_rm[(ty * 8 + r) * out_stride + tx + 64 * jj] = fmaxf(s, 0.01f * s);
        }
    }
}

extern __shared__ float sm[];

__global__ void __launch_bounds__(NTHREADS, 1)
udp_encoder_kernel(
    const float* __restrict__ obs,  const float* __restrict__ act,
    const float* __restrict__ obs2, const float* __restrict__ rew,
    const float* __restrict__ b0,   const float* __restrict__ b1,
    const float* __restrict__ b2,   const float* __restrict__ Wp,
    const float* __restrict__ ee,   const float* __restrict__ sig,
    float* __restrict__ out)
{
    const int tid = threadIdx.x;
    const size_t row0 = (size_t)blockIdx.x * ROWS;

    // ---- stage e_emb + sigma coefficients ----
    for (int i = tid; i < NENV * EMB; i += NTHREADS) sm[OFF_EEMB + i] = ee[i];
    if (tid < NENV) {
        float s = sig[tid];
        sm[OFF_COEF + tid] = -1.0f / (64.0f * s * s);
    }

    // ---- build row-major input tile X[r][k], stride 164, k=145..159 zero ----
    for (int i = tid; i < ROWS * OBS; i += NTHREADS) {
        int r = i >> 6, k = i & 63;
        float o  = obs [(row0 + r) * OBS + k];
        float o2 = obs2[(row0 + r) * OBS + k];
        sm[OFF_X + r * XS + k]      = o;
        sm[OFF_X + r * XS + 64 + k] = o2 - o;
    }
    for (int i = tid; i < ROWS * ACTD; i += NTHREADS) {
        int r = i >> 4, k = i & 15;
        sm[OFF_X + r * XS + 128 + k] = act[(row0 + r) * ACTD + k];
    }
    if (tid < ROWS) {
        sm[OFF_X + tid * XS + 144] = rew[row0 + tid];
#pragma unroll
        for (int k = 145; k < 160; k++) sm[OFF_X + tid * XS + k] = 0.0f;
    }
    __syncthreads();

    float4* sb0 = (float4*)(sm + OFF_STG);
    float4* sb1 = sb0 + 1024;

    // ---- MLP (cp.async weight streaming) ----
    dense_cp<4, 10>(sm + OFF_X,  XS, g_w0q, b0, 256, sm + OFF_H0,   HS, sb0, sb1, tid);
    dense_cp<4, 16>(sm + OFF_H0, HS, g_w1q, b1, 256, sm + OFF_H1,   HS, sb0, sb1, tid);
    dense_cp<2, 16>(sm + OFF_H1, HS, g_w2q, b2, 128, sm + OFF_FEAT, FS, sb0, sb1, tid);
    __syncthreads();   // feat final; H0/H1/STG now dead

    // ==== projection: two independent halves over env-groups ====
    const int lane = tid & 31;
    const int wrp  = tid >> 5;          // 16 warps
    const int h    = wrp >> 3;          // half 0: g 0..7 ; half 1: g 8..15
    const int wr   = wrp & 7;           // row-warp within half, 8 rows each
    const int nl   = lane >> 3;         // env within group (0..3)
    const int eb   = lane & 7;          // lane's emb dims: e = eb + 8j
    const int r0   = wr * 8;

    float mind[8]; int midx[8];
#pragma unroll
    for (int i = 0; i < 8; i++) { mind[i] = 3.0e38f; midx[i] = 0; }

    float4* wt = (float4*)(sm + (h ? OFF_TB : OFF_TA));   // [c][kq], stride 33 f4
    float*  bestH = sm + (h ? OFF_BESTB : OFF_BESTA);
    const float4* WpQ = (const float4*)Wp;                // [n][e][kq]
    const float* fbase = sm + OFF_FEAT + r0 * FS;

    for (int gg = 0; gg < 8; gg++) {
        const int g = h * 8 + gg;
        bar_half(h);
        // stage W tile: warp wr covers c = wr + 8*i; lane = kq
#pragma unroll
        for (int i = 0; i < 16; i++) {
            int c = wr + 8 * i;
            int n_l = c >> 5, e = c & 31;
            float4 v = WpQ[((size_t)(g * 4 + n_l) * EMB + e) * 32 + lane];
            wt[c * 33 + lane] = v;
        }
        bar_half(h);

        const int n = g * 4 + nl;
        float eev[4];
#pragma unroll
        for (int j = 0; j < 4; j++) eev[j] = sm[OFF_EEMB + n * EMB + eb + 8 * j];
        float cf = sm[OFF_COEF + n];

        u64 acc[8][4];
#pragma unroll
        for (int r = 0; r < 8; r++)
#pragma unroll
            for (int j = 0; j < 4; j++) acc[r][j] = 0ULL;

#pragma unroll 2
        for (int kq = 0; kq < 32; kq++) {
            ulonglong2 w[4];
#pragma unroll
            for (int j = 0; j < 4; j++)
                w[j] = *(const ulonglong2*)&wt[(nl * 32 + eb + 8 * j) * 33 + kq];
#pragma unroll
            for (int r = 0; r < 8; r++) {
                ulonglong2 xq = *(const ulonglong2*)(fbase + r * FS + 4 * kq);
#pragma unroll
                for (int j = 0; j < 4; j++) {
                    acc[r][j] = fma2(xq.x, w[j].x, acc[r][j]);
                    acc[r][j] = fma2(xq.y, w[j].y, acc[r][j]);
                }
            }
        }

        // epilogue: distances, argmin, winner-copy — all in-warp
#pragma unroll
        for (int r = 0; r < 8; r++) {
            float f[4];
#pragma unroll
            for (int j = 0; j < 4; j++) {
                float lo, hi; unpack2(acc[r][j], lo, hi);
                f[j] = lo + hi;
            }
            float ss = 0.0f;
#pragma unroll
            for (int j = 0; j < 4; j++) {
                float d = f[j] - eev[j];
                ss = fmaf(d, d, ss);
            }
            ss += __shfl_xor_sync(0xffffffffu, ss, 1);
            ss += __shfl_xor_sync(0xffffffffu, ss, 2);
            ss += __shfl_xor_sync(0xffffffffu, ss, 4);
            float dv = expf(ss * cf);
            if (eb == 0)
                out[(size_t)B_TOTAL * 66 + (row0 + r0 + r) * 64 + n] = dv;

            float dred = (eb == 0) ? dv : 3.0e38f;
            int   nred = n;
#pragma unroll
            for (int s = 8; s <= 16; s <<= 1) {
                float d2 = __shfl_xor_sync(0xffffffffu, dred, s);
                int   n2 = __shfl_xor_sync(0xffffffffu, nred, s);
                if (d2 < dred || (d2 == dred && n2 < nred)) { dred = d2; nred = n2; }
            }
            float wd = __shfl_sync(0xffffffffu, dred, 0);
            int   wn2 = __shfl_sync(0xffffffffu, nred, 0);

            if (wd < mind[r]) {
                mind[r] = wd; midx[r] = wn2;
                if (nl == (wn2 & 3)) {
#pragma unroll
                    for (int j = 0; j < 4; j++)
                        bestH[(r0 + r) * EMB + eb + 8 * j] = f[j];
                }
            }
        }
    }

    // publish per-half argmin state
    if (lane == 0) {
        float* minH = sm + (h ? OFF_MINB : OFF_MINA);
        int*   idxH = (int*)sm + (h ? OFF_IDXB : OFF_IDXA);
#pragma unroll
        for (int r = 0; r < 8; r++) {
            minH[r0 + r] = mind[r];
            idxH[r0 + r] = midx[r];
        }
    }
    __syncthreads();

    // ==== combine halves + final outputs: each warp handles 4 rows ====
#pragma unroll
    for (int r = 0; r < 4; r++) {
        int row = wrp * 4 + r;
        size_t grow = row0 + row;
        float da = sm[OFF_MINA + row], db = sm[OFF_MINB + row];
        bool bwin = db < da;   // half A owns smaller n -> wins ties
        float d = bwin ? db : da;
        int m = bwin ? ((int*)sm)[OFF_IDXB + row] : ((int*)sm)[OFF_IDXA + row];
        float e = bwin ? sm[OFF_BESTB + row * EMB + lane]
                       : sm[OFF_BESTA + row * EMB + lane];
        out[grow * EMB + lane] = e;                                                    // chosen_embedding
        out[(size_t)B_TOTAL * 34 + grow * EMB + lane] = sm[OFF_EEMB + m * EMB + lane]; // chosen_mean
        if (lane == 0) {
            out[(size_t)B_TOTAL * 32 + grow] = d;          // chosen_dist
            out[(size_t)B_TOTAL * 33 + grow] = (float)m;   // idx
        }
    }
}

extern "C" void kernel_launch(void* const* d_in, const int* in_sizes, int n_in,
                              void* d_out, int out_size) {
    const float* obs  = (const float*)d_in[0];
    const float* act  = (const float*)d_in[1];
    const float* obs2 = (const float*)d_in[2];
    const float* rew  = (const float*)d_in[3];
    const float* W0   = (const float*)d_in[4];
    const float* b0   = (const float*)d_in[5];
    const float* W1   = (const float*)d_in[6];
    const float* b1   = (const float*)d_in[7];
    const float* W2   = (const float*)d_in[8];
    const float* b2   = (const float*)d_in[9];
    const float* Wp   = (const float*)d_in[10];
    const float* ee   = (const float*)d_in[11];
    const float* sig  = (const float*)d_in[12];
    float* out = (float*)d_out;

    int total = KQ0 * 256 + KQ1 * 256 + KQ2 * 128;
    repack_kernel<<<(total + 255) / 256, 256>>>(W0, W1, W2);

    const size_t smem_bytes = (size_t)SMEM_FLOATS * sizeof(float); // 231680
    cudaFuncSetAttribute(udp_encoder_kernel,
                         cudaFuncAttributeMaxDynamicSharedMemorySize, (int)smem_bytes);

    dim3 grid(B_TOTAL / ROWS);   // 1024 blocks
    dim3 block(NTHREADS);
    udp_encoder_kernel<<<grid, block, smem_bytes>>>(
        obs, act, obs2, rew, b0, b1, b2, Wp, ee, sig, out);
}